// round 14
// baseline (speedup 1.0000x reference)
#include <cuda_runtime.h>
#include <cuda_fp16.h>
#include <math.h>
#include <stdint.h>

#define IN_DIM   2048
#define OUT_DIM  2048
#define RNK      4
#define LUTN     16
#define NORM_EPS 1e-6f
#define MAG_EPS  1e-6f

// GEMM config: single-pass fp16, K = 2048, paired-chunk mbarrier ring
#define NSTEP   64               // 2048 / 32 chunks, consumed in 32 pairs
#define STAGES  4
#define ROWB    80               // 32 fp16 = 64B data + 16B pad (5 coprime 8 -> conflict-free ldsm)
#define ATILE_BYTES (128 * ROWB) // 10240
#define STAGE_BYTES (2 * ATILE_BYTES)
#define SMEM_TOTAL  (128 + STAGES * STAGE_BYTES)   // 82048 -> 2 CTAs/SM

// ---------------- device scratch ----------------
__device__ float d_nA[RNK];
__device__ float d_nB[RNK];
__device__ float d_g[RNK];
__device__ int   d_done = 0;     // prep->W ordering flag; reset by gemm_kernel each launch
__device__ __align__(1024) __half d_Ah[(size_t)8192 * IN_DIM];     // x as fp16 [M, 2048]
__device__ __align__(1024) __half d_Bh[(size_t)OUT_DIM * IN_DIM];  // W as fp16 [N, 2048]

// ---------------- PTX helpers (plain sm_103-safe: sm_80/sm_90 features) ----------------
__device__ __forceinline__ uint32_t smem_u32(const void* p) {
    uint32_t a;
    asm("{ .reg .u64 t; cvta.to.shared.u64 t, %1; cvt.u32.u64 %0, t; }" : "=r"(a) : "l"(p));
    return a;
}
#define CP_ASYNC16(s, g) \
    asm volatile("cp.async.cg.shared.global [%0], [%1], 16;" :: "r"(s), "l"(g) : "memory")
#define MBAR_INIT(a, c) \
    asm volatile("mbarrier.init.shared.b64 [%0], %1;" :: "r"(a), "r"(c) : "memory")
#define MBAR_ARRIVE(a) \
    asm volatile("mbarrier.arrive.shared.b64 _, [%0];" :: "r"(a) : "memory")
#define CP_MBAR_ARRIVE(a) \
    asm volatile("cp.async.mbarrier.arrive.noinc.shared.b64 [%0];" :: "r"(a) : "memory")

__device__ __forceinline__ void mbar_wait(uint32_t mbar, uint32_t parity) {
    asm volatile(
        "{\n\t.reg .pred P;\n\t"
        "W%=:\n\t"
        "mbarrier.try_wait.parity.acquire.cta.shared::cta.b64 P, [%0], %1, 0x989680;\n\t"
        "@P bra.uni D%=;\n\t"
        "bra.uni W%=;\n\t"
        "D%=:\n\t}"
        :: "r"(mbar), "r"(parity) : "memory");
}

__device__ __forceinline__ void ldm_x4(uint32_t& r0, uint32_t& r1, uint32_t& r2, uint32_t& r3,
                                       uint32_t addr) {
    asm volatile("ldmatrix.sync.aligned.m8n8.x4.shared.b16 {%0,%1,%2,%3}, [%4];"
                 : "=r"(r0), "=r"(r1), "=r"(r2), "=r"(r3) : "r"(addr));
}
__device__ __forceinline__ void mma_f16(float& c0, float& c1, float& c2, float& c3,
                                        uint32_t a0, uint32_t a1, uint32_t a2, uint32_t a3,
                                        uint32_t b0, uint32_t b1) {
    asm volatile(
        "mma.sync.aligned.m16n8k16.row.col.f32.f16.f16.f32 "
        "{%0,%1,%2,%3}, {%4,%5,%6,%7}, {%8,%9}, {%0,%1,%2,%3};"
        : "+f"(c0), "+f"(c1), "+f"(c2), "+f"(c3)
        : "r"(a0), "r"(a1), "r"(a2), "r"(a3), "r"(b0), "r"(b1));
}

// ---------------- kernel 1: fused prep-norms + convert x + build W ----------------
__global__ void convert_kernel(const float* __restrict__ x,
                               const int* __restrict__ idx,
                               const float* __restrict__ lut,
                               const float* __restrict__ sA,
                               const float* __restrict__ sB,
                               const float* __restrict__ mag,
                               int xblk) {
    const int bid = blockIdx.x;

    if (bid < 8) {
        // ---- norms ----
        __shared__ float red[8];
        int tid = threadIdx.x, lane = tid & 31, w = tid >> 5;
        int r = bid & 3;
        float s = 0.f;
        if (bid < 4) {
            for (int o = tid; o < OUT_DIM; o += 256) { float v = sA[o * RNK + r]; s += v * v; }
        } else {
            for (int i = tid; i < IN_DIM; i += 256) { float v = sB[r * IN_DIM + i]; s += v * v; }
        }
        #pragma unroll
        for (int off = 16; off; off >>= 1) s += __shfl_xor_sync(0xffffffffu, s, off);
        if (lane == 0) red[w] = s;
        __syncthreads();
        if (tid == 0) {
            float t = 0.f;
            #pragma unroll
            for (int i = 0; i < 8; i++) t += red[i];
            float n = fmaxf(sqrtf(t), NORM_EPS);
            if (bid < 4) d_nA[r] = n; else d_nB[r] = n;
            if (bid == 0) {
                #pragma unroll
                for (int q = 0; q < RNK; q++) {
                    float m = mag[q];
                    float sp = (m > 20.f) ? m : log1pf(expf(m));
                    d_g[q] = sp + MAG_EPS;
                }
            }
            __threadfence();
            atomicAdd(&d_done, 1);
        }
        return;
    }

    if (bid < 8 + xblk) {
        // ---- x -> fp16 ----
        size_t t = (size_t)(bid - 8) * blockDim.x + threadIdx.x;
        size_t base = t * 4;
        float4 v = *(const float4*)(x + base);
        __half2 h0 = __floats2half2_rn(v.x, v.y);
        __half2 h1 = __floats2half2_rn(v.z, v.w);
        *(uint2*)&d_Ah[base] = make_uint2(*(uint32_t*)&h0, *(uint32_t*)&h1);
        return;
    }

    // ---- build W (needs norms) ----
    __shared__ float lutS[LUTN];
    if (threadIdx.x < LUTN) lutS[threadIdx.x] = lut[threadIdx.x];
    if (threadIdx.x == 0) {
        while (atomicAdd(&d_done, 0) < 8) {}
        __threadfence();
    }
    __syncthreads();

    size_t t = (size_t)(bid - 8 - xblk) * blockDim.x + threadIdx.x;
    size_t base = t * 4;
    int o = (int)(base >> 11);
    int i0 = (int)(base & 2047);

    float cA[RNK];
    #pragma unroll
    for (int r = 0; r < RNK; r++)
        cA[r] = fabsf(sA[o * RNK + r]) * d_g[r] / (d_nA[r] * d_nB[r]);

    int4 id4 = *(const int4*)(idx + (size_t)o * IN_DIM + i0);
    int ids[4] = {id4.x, id4.y, id4.z, id4.w};
    float w[4];
    #pragma unroll
    for (int j = 0; j < 4; j++) {
        int i = i0 + j;
        float s = 0.f;
        #pragma unroll
        for (int r = 0; r < RNK; r++)
            s += cA[r] * fabsf(sB[r * IN_DIM + i]);
        w[j] = lutS[ids[j]] * s;
    }
    __half2 h0 = __floats2half2_rn(w[0], w[1]);
    __half2 h1 = __floats2half2_rn(w[2], w[3]);
    *(uint2*)&d_Bh[base] = make_uint2(*(uint32_t*)&h0, *(uint32_t*)&h1);
}

// ---------------- kernel 2: fp16 GEMM, paired-chunk mbarrier ring, 2 CTAs/SM ----------------
__global__ __launch_bounds__(256, 2)
void gemm_kernel(const float* __restrict__ bias, float* __restrict__ y) {
    // reset the prep flag for the NEXT launch (stream-ordered after convert consumed it)
    if (blockIdx.x == 0 && blockIdx.y == 0 && threadIdx.x == 0) d_done = 0;

    extern __shared__ char smem[];
    const uint32_t sbase = smem_u32(smem);
    const uint32_t mbF = sbase;           // full[4]
    const uint32_t mbE = sbase + 64;      // empty[4] (only odd slots waited on)
    const uint32_t dbase = sbase + 128;

    const int tid = threadIdx.x, lane = tid & 31, wid = tid >> 5;
    const int warp_m = wid & 1, warp_n = wid >> 1;     // 2 x 4 warps, 64x32 warp tiles
    const int m0 = blockIdx.y * 128, n0 = blockIdx.x * 128;

    const int lr = tid >> 2, lc = tid & 3;
    const __half* Ag = d_Ah + (size_t)m0 * IN_DIM;
    const __half* Bg = d_Bh + (size_t)n0 * IN_DIM;

    const uint32_t aLaneOff = (uint32_t)(lane & 15) * ROWB + (uint32_t)(lane >> 4) * 16;
    const uint32_t bLaneOff = (uint32_t)((lane & 7) + ((lane >> 4) << 3)) * ROWB
                            + (uint32_t)((lane >> 3) & 1) * 16;

    if (tid == 0) {
        #pragma unroll
        for (int s = 0; s < STAGES; s++) {
            MBAR_INIT(mbF + s * 8, 256);   // every thread's cp.async arrive (noinc)
            MBAR_INIT(mbE + s * 8, 8);     // one arrive per warp (per pair, on odd slot)
        }
    }
    __syncthreads();

    float acc[4][4][4];
    #pragma unroll
    for (int i = 0; i < 4; i++)
        #pragma unroll
        for (int j = 0; j < 4; j++)
            #pragma unroll
            for (int q = 0; q < 4; q++) acc[i][j][q] = 0.f;

    auto issue_cp = [&](int c) {
        int slot = c & 3;
        int kk = c << 5;
        uint32_t sA = dbase + slot * STAGE_BYTES;
        uint32_t sB = sA + ATILE_BYTES;
        CP_ASYNC16(sA + lr * ROWB + lc * 16,
                   (const char*)(Ag + (size_t)lr * IN_DIM + kk + lc * 8));
        CP_ASYNC16(sA + (lr + 64) * ROWB + lc * 16,
                   (const char*)(Ag + (size_t)(lr + 64) * IN_DIM + kk + lc * 8));
        CP_ASYNC16(sB + lr * ROWB + lc * 16,
                   (const char*)(Bg + (size_t)lr * IN_DIM + kk + lc * 8));
        CP_ASYNC16(sB + (lr + 64) * ROWB + lc * 16,
                   (const char*)(Bg + (size_t)(lr + 64) * IN_DIM + kk + lc * 8));
        CP_MBAR_ARRIVE(mbF + slot * 8);
    };

    auto consume = [&](int slot) {
        uint32_t sA = dbase + slot * STAGE_BYTES + (uint32_t)(warp_m * 64) * ROWB + aLaneOff;
        uint32_t sB = dbase + slot * STAGE_BYTES + ATILE_BYTES
                    + (uint32_t)(warp_n * 32) * ROWB + bLaneOff;
        #pragma unroll
        for (int k16 = 0; k16 < 2; k16++) {
            uint32_t a[4][4], b[2][4];
            #pragma unroll
            for (int mi = 0; mi < 4; mi++)
                ldm_x4(a[mi][0], a[mi][1], a[mi][2], a[mi][3],
                       sA + (uint32_t)(mi * 16) * ROWB + k16 * 32);
            #pragma unroll
            for (int p = 0; p < 2; p++)
                ldm_x4(b[p][0], b[p][1], b[p][2], b[p][3],
                       sB + (uint32_t)(p * 16) * ROWB + k16 * 32);
            #pragma unroll
            for (int mi = 0; mi < 4; mi++)
                #pragma unroll
                for (int ni = 0; ni < 4; ni++) {
                    uint32_t b0 = b[ni >> 1][(ni & 1) * 2];
                    uint32_t b1 = b[ni >> 1][(ni & 1) * 2 + 1];
                    mma_f16(acc[mi][ni][0], acc[mi][ni][1], acc[mi][ni][2], acc[mi][ni][3],
                            a[mi][0], a[mi][1], a[mi][2], a[mi][3], b0, b1);
                }
        }
    };

    // prologue: fill pair (0,1)
    issue_cp(0); issue_cp(1);

    for (int t = 0; t < NSTEP; t += 2) {
        // produce next pair (t+2, t+3): one empty-wait on the later chunk
        int tf = t + 2;
        if (tf < NSTEP) {
            int c2 = tf + 1;
            if (c2 >= STAGES)
                mbar_wait(mbE + (c2 & 3) * 8, ((c2 >> 2) + 1) & 1);
            issue_cp(tf);
            issue_cp(c2);
        }

        // consume pair (t, t+1): one full-wait on the later chunk
        int cl = t + 1;
        mbar_wait(mbF + (cl & 3) * 8, (cl >> 2) & 1);   // implies full(t) too (per-thread FIFO)

        consume(t & 3);
        consume(cl & 3);

        __syncwarp();
        if (lane == 0) MBAR_ARRIVE(mbE + (cl & 3) * 8);  // pair done (odd slot covers both)
    }

    // ---- epilogue: + bias, float2 stores (per-warp independent) ----
    #pragma unroll
    for (int ni = 0; ni < 4; ni++) {
        int col = n0 + warp_n * 32 + ni * 8 + (lane & 3) * 2;
        float2 bb = *(const float2*)(bias + col);
        #pragma unroll
        for (int mi = 0; mi < 4; mi++) {
            int r0 = m0 + warp_m * 64 + mi * 16 + (lane >> 2);
            float2 v0, v1;
            v0.x = acc[mi][ni][0] + bb.x; v0.y = acc[mi][ni][1] + bb.y;
            v1.x = acc[mi][ni][2] + bb.x; v1.y = acc[mi][ni][3] + bb.y;
            *(float2*)(y + (size_t)r0 * OUT_DIM + col)       = v0;
            *(float2*)(y + (size_t)(r0 + 8) * OUT_DIM + col) = v1;
        }
    }
}

// ---------------- host ----------------
extern "C" void kernel_launch(void* const* d_in, const int* in_sizes, int n_in,
                              void* d_out, int out_size) {
    const float* x       = (const float*)d_in[0];
    const int*   indices = (const int*)d_in[1];
    const float* lut     = (const float*)d_in[2];
    const float* sA      = (const float*)d_in[3];
    const float* sB      = (const float*)d_in[4];
    const float* mag     = (const float*)d_in[5];
    const float* bias    = (const float*)d_in[6];
    float*       y       = (float*)d_out;

    int M = in_sizes[0] / IN_DIM;   // 8192
    int xblk = (int)((size_t)M * IN_DIM / 4 / 256);          // 16384
    int wblk = (OUT_DIM * IN_DIM / 4) / 256;                 // 4096

    cudaFuncSetAttribute(gemm_kernel, cudaFuncAttributeMaxDynamicSharedMemorySize, SMEM_TOTAL);

    convert_kernel<<<8 + xblk + wblk, 256>>>(x, indices, lut, sA, sB, mag, xblk);
    gemm_kernel<<<dim3(OUT_DIM / 128, M / 128), 256, SMEM_TOTAL>>>(bias, y);
}